// round 4
// baseline (speedup 1.0000x reference)
#include <cuda_runtime.h>

#define NC 80
#define CH 85
#define NB 16      // batch
#define NM 64      // boxes per image
#define NA 3       // anchors per layer

// Layer sizes
#define N0 307200  // 16*3*80*80
#define N1 76800   // 16*3*40*40
#define N2 19200   // 16*3*20*20

// obj blocks: 256 threads x 8 elems = 2048 elems per block
#define OB0 150            // 307200/2048
#define OB1 38             // ceil(76800/2048)
#define OB2 10             // ceil(19200/2048)
#define NOBJ (OB0 + OB1 + OB2)   // 198

#define NBOXBLK 48         // 3 layers * 16 batch images
#define TOTBLK (NBOXBLK + NOBJ)  // 246

__device__ float4 g_box_part[NBOXBLK];   // {cls, bbox, corr, npos} per (l,b)
__device__ float  g_obj_part[NOBJ];
__device__ int    g_done;                // zero-init in .bss; finisher resets

__device__ __forceinline__ float softplus0(float x) {
    // BCE(x, 0) = max(x,0) + log1p(exp(-|x|))
    return fmaxf(x, 0.0f) + log1pf(__expf(-fabsf(x)));
}

__global__ void __launch_bounds__(256)
fused_kernel(const float* __restrict__ p3,
             const float* __restrict__ p4,
             const float* __restrict__ p5,
             const float* __restrict__ boxes,
             const int*   __restrict__ labels,
             const unsigned char* __restrict__ valid,
             const float* __restrict__ anchors,
             float* __restrict__ out)
{
    const int bid = blockIdx.x;
    const int tid = threadIdx.x;
    const int wid = tid >> 5, lid = tid & 31;

    __shared__ float s_f[4][8];
    __shared__ int   s_table[256];
    __shared__ int   s_ticket;

    if (bid < NBOXBLK) {
        // ================= BOX WORK: one block per (layer, batch) ==========
        const int l = bid >> 4;
        const int b = bid & 15;
        const int g = (l == 0) ? 80 : (l == 1) ? 40 : 20;
        const float* pred = (l == 0) ? p3 : (l == 1) ? p4 : p5;

        const int m = tid >> 2;          // box 0..63
        const int q = tid & 3;           // sub-lane 0..3 (20 classes each)

        s_table[tid] = -1;

        const float aw0 = anchors[l * 6 + 0], ah0 = anchors[l * 6 + 1];
        const float aw1 = anchors[l * 6 + 2], ah1 = anchors[l * 6 + 3];
        const float aw2 = anchors[l * 6 + 4], ah2 = anchors[l * 6 + 5];

        const int bm = b * NM + m;
        const float4 bx = ((const float4*)boxes)[bm];
        const float gf = (float)g;
        const float cx = (bx.x + bx.z) * 0.5f * gf;
        const float cy = (bx.y + bx.w) * 0.5f * gf;
        const float w  = (bx.z - bx.x) * gf;
        const float h  = (bx.w - bx.y) * gf;

        const float wh = w * h;
        const float i0 = fminf(w, aw0) * fminf(h, ah0);
        const float i1 = fminf(w, aw1) * fminf(h, ah1);
        const float i2 = fminf(w, aw2) * fminf(h, ah2);
        const float iou0 = i0 / (wh + aw0 * ah0 - i0 + 1e-6f);
        const float iou1 = i1 / (wh + aw1 * ah1 - i1 + 1e-6f);
        const float iou2 = i2 / (wh + aw2 * ah2 - i2 + 1e-6f);

        int besta = 0; float bi = iou0;
        if (iou1 > bi) { bi = iou1; besta = 1; }
        if (iou2 > bi) { bi = iou2; besta = 2; }

        const bool pos = (valid[bm] != 0) && (bi > 0.5f);
        const int gx = min(max((int)cx, 0), g - 1);
        const int gy = min(max((int)cy, 0), g - 1);
        const int key = ((b * NA + besta) * g + gy) * g + gx;

        __syncthreads();   // table init complete

        float cls = 0.0f, bbox = 0.0f, corr = 0.0f, np = 0.0f;

        if (pos) {
            const float* pp = pred + (size_t)key * CH;

            // --- cls: 20 of the 80 class channels (stride 4 for coalescing) ---
            #pragma unroll
            for (int k = 0; k < 20; k++) cls += softplus0(pp[5 + q + 4 * k]);

            if (q == 0) {
                np = 1.0f;
                cls -= pp[5 + labels[bm]];

                // dedup: first claimant of this cell applies obj correction
                bool first = false;
                unsigned hsh = ((unsigned)key * 2654435761u) & 255u;
                while (true) {
                    int old = atomicCAS(&s_table[hsh], -1, key);
                    if (old == -1) { first = true; break; }
                    if (old == key) { break; }
                    hsh = (hsh + 1u) & 255u;
                }
                if (first) corr = -pp[4];   // BCE(x,1) - BCE(x,0) == -x

                // --- CIoU (exact replication of reference arithmetic) ---
                float pcx = pp[0], pcy = pp[1], pw = pp[2], ph = pp[3];
                float px1 = pcx - pw * 0.5f, py1 = pcy - ph * 0.5f;
                float px2 = pcx + pw * 0.5f, py2 = pcy + ph * 0.5f;
                float tx1 = cx - w * 0.5f, ty1 = cy - h * 0.5f;
                float tx2 = cx + w * 0.5f, ty2 = cy + h * 0.5f;
                float ix1 = fmaxf(px1, tx1), iy1 = fmaxf(py1, ty1);
                float ix2 = fminf(px2, tx2), iy2 = fminf(py2, ty2);
                float inter = fmaxf(ix2 - ix1, 0.0f) * fmaxf(iy2 - iy1, 0.0f);
                float a1 = (px2 - px1) * (py2 - py1);
                float a2 = (tx2 - tx1) * (ty2 - ty1);
                float iou = inter / (a1 + a2 - inter + 1e-7f);
                float ccx = (px1 + px2) * 0.5f, ccy = (py1 + py2) * 0.5f;
                float dcx = (tx1 + tx2) * 0.5f, dcy = (ty1 + ty2) * 0.5f;
                float cd = (ccx - dcx) * (ccx - dcx) + (ccy - dcy) * (ccy - dcy);
                float ex1 = fminf(px1, tx1), ey1 = fminf(py1, ty1);
                float ex2 = fmaxf(px2, tx2), ey2 = fmaxf(py2, ty2);
                float dd = (ex2 - ex1) * (ex2 - ex1) + (ey2 - ey1) * (ey2 - ey1);
                bbox = 1.0f - (iou - cd / (dd + 1e-7f));
            }
        }

        // block reduction of {cls, bbox, corr, np}
        #pragma unroll
        for (int o = 16; o > 0; o >>= 1) {
            cls  += __shfl_down_sync(0xffffffffu, cls,  o);
            bbox += __shfl_down_sync(0xffffffffu, bbox, o);
            corr += __shfl_down_sync(0xffffffffu, corr, o);
            np   += __shfl_down_sync(0xffffffffu, np,   o);
        }
        if (lid == 0) { s_f[0][wid] = cls; s_f[1][wid] = bbox; s_f[2][wid] = corr; s_f[3][wid] = np; }
        __syncthreads();
        if (wid == 0) {
            cls  = (lid < 8) ? s_f[0][lid] : 0.0f;
            bbox = (lid < 8) ? s_f[1][lid] : 0.0f;
            corr = (lid < 8) ? s_f[2][lid] : 0.0f;
            np   = (lid < 8) ? s_f[3][lid] : 0.0f;
            #pragma unroll
            for (int o = 4; o > 0; o >>= 1) {
                cls  += __shfl_down_sync(0xffffffffu, cls,  o);
                bbox += __shfl_down_sync(0xffffffffu, bbox, o);
                corr += __shfl_down_sync(0xffffffffu, corr, o);
                np   += __shfl_down_sync(0xffffffffu, np,   o);
            }
            if (lid == 0) g_box_part[bid] = make_float4(cls, bbox, corr, np);
        }
    } else {
        // ================= OBJ STREAMING =====================================
        const int ob = bid - NBOXBLK;
        const float* p; int n, lb;
        if (ob < OB0)            { p = p3; n = N0; lb = ob; }
        else if (ob < OB0 + OB1) { p = p4; n = N1; lb = ob - OB0; }
        else                     { p = p5; n = N2; lb = ob - OB0 - OB1; }

        const int base = lb * 2048 + tid;
        float s = 0.0f;
        #pragma unroll
        for (int k = 0; k < 8; k++) {
            int i = base + k * 256;
            if (i < n) {
                float x = __ldg(&p[(size_t)i * CH + 4]);
                s += fmaxf(x, 0.0f) + log1pf(__expf(-fabsf(x)));
            }
        }

        #pragma unroll
        for (int o = 16; o > 0; o >>= 1) s += __shfl_down_sync(0xffffffffu, s, o);
        if (lid == 0) s_f[0][wid] = s;
        __syncthreads();
        if (wid == 0) {
            s = (lid < 8) ? s_f[0][lid] : 0.0f;
            #pragma unroll
            for (int o = 4; o > 0; o >>= 1) s += __shfl_down_sync(0xffffffffu, s, o);
            if (lid == 0) g_obj_part[ob] = s;
        }
    }

    // ================= LAST-BLOCK FINALIZE ===================================
    __threadfence();
    if (tid == 0) s_ticket = atomicAdd(&g_done, 1);
    __syncthreads();

    if (s_ticket == TOTBLK - 1) {
        __threadfence();
        if (wid == 0) {
            const int start[4] = {0, OB0, OB0 + OB1, NOBJ};
            const float cells[3] = {(float)N0, (float)N1, (float)N2};
            float tot = 0.0f;
            #pragma unroll
            for (int l = 0; l < 3; l++) {
                float s = 0.0f;
                for (int i = start[l] + lid; i < start[l + 1]; i += 32)
                    s += g_obj_part[i];
                float cls = 0.0f, bbox = 0.0f, corr = 0.0f, np = 0.0f;
                if (lid < 16) {
                    float4 v = g_box_part[l * 16 + lid];
                    cls = v.x; bbox = v.y; corr = v.z; np = v.w;
                }
                #pragma unroll
                for (int o = 16; o > 0; o >>= 1) {
                    s    += __shfl_down_sync(0xffffffffu, s,    o);
                    cls  += __shfl_down_sync(0xffffffffu, cls,  o);
                    bbox += __shfl_down_sync(0xffffffffu, bbox, o);
                    corr += __shfl_down_sync(0xffffffffu, corr, o);
                    np   += __shfl_down_sync(0xffffffffu, np,   o);
                }
                if (lid == 0 && np > 0.0f) {
                    tot += 0.5f  * (cls / (np * (float)NC))
                         +         ((s + corr) / cells[l])
                         + 0.05f * (bbox / np);
                }
            }
            if (lid == 0) {
                out[0] = tot;
                __threadfence();
                g_done = 0;   // reset for next graph replay
            }
        }
    }
}

extern "C" void kernel_launch(void* const* d_in, const int* in_sizes, int n_in,
                              void* d_out, int out_size)
{
    const float* p3     = (const float*)d_in[0];
    const float* p4     = (const float*)d_in[1];
    const float* p5     = (const float*)d_in[2];
    const float* boxes  = (const float*)d_in[3];
    const int*   labels = (const int*)d_in[4];
    const unsigned char* valid = (const unsigned char*)d_in[5];
    const float* anchors = (const float*)d_in[6];

    fused_kernel<<<TOTBLK, 256>>>(p3, p4, p5, boxes, labels, valid, anchors,
                                  (float*)d_out);
}